// round 1
// baseline (speedup 1.0000x reference)
#include <cuda_runtime.h>
#include <cstdint>

#define NG   262144          // graphs
#define NPG  6               // nodes per graph
#define NN   (NG*NPG)        // nodes
#define FD   13              // input features
#define HD   32              // hidden
#define GD   9               // global features
#define EPG  30              // directed edges per graph (6-clique)
#define BNEPS 1e-5f

// ---------------- scratch (static device allocations; no cudaMalloc) ----------------
__device__ float g_h1[(size_t)NN * HD];   // 201 MB  layer1 pre-BN
__device__ float g_h2[(size_t)NN * HD];   // 201 MB  layer2 pre-BN
__device__ float g_sum1[HD], g_sq1[HD], g_sum2[HD], g_sq2[HD];
__device__ float g_scale1[HD], g_shift1[HD], g_scale2[HD], g_shift2[HD];

// ---------------- helpers ----------------
__global__ void k_zero_stats() {
    int i = threadIdx.x;
    if (i < HD) { g_sum1[i] = 0.f; g_sq1[i] = 0.f; g_sum2[i] = 0.f; g_sq2[i] = 0.f; }
}

// Each lane t<6 computes deg[t] = 1 + sum of incoming edge weights, then all
// lanes receive dv[s] = rsqrt(deg[s]) for s=0..5.
// we = edge weight held by lane k<30 for edge (s=k/5 -> t), within-graph order.
__device__ __forceinline__ void dinv6(float we, int lane, float dv[6]) {
    float d = 1.0f;
    int t = lane;
    #pragma unroll
    for (int s = 0; s < 6; s++) {
        // incoming edge (s->t) sits at k = s*5 + (t<s ? t : t-1)
        int idx = (s * 5 + (t < s ? t : t - 1)) & 31;
        float w = __shfl_sync(0xffffffffu, we, idx);
        if (t < 6 && s != t) d += w;
    }
    float dvt = (t < 6) ? rsqrtf(d) : 0.f;
    #pragma unroll
    for (int s = 0; s < 6; s++) dv[s] = __shfl_sync(0xffffffffu, dvt, s);
}

// ---------------- K1: h1_pre = (A @ x) @ W1 + b1 ; accumulate BN1 stats ----------------
__global__ void __launch_bounds__(256) k1(const float* __restrict__ x,
                                          const float* __restrict__ ew,
                                          const float* __restrict__ W1,
                                          const float* __restrict__ b1) {
    __shared__ float sbuf[8][208];   // per warp: sx[0..77], sA[80..115], sxa[120..197]
    __shared__ float sred[8][64];
    const int lane = threadIdx.x & 31, w = threadIdx.x >> 5;
    float* sx  = sbuf[w];
    float* sA  = sbuf[w] + 80;
    float* sxa = sbuf[w] + 120;

    float w1c[FD];
    #pragma unroll
    for (int c = 0; c < FD; c++) w1c[c] = W1[c * HD + lane];
    const float b1l = b1[lane];

    float ssum = 0.f, ssq = 0.f;
    const int warpId = (blockIdx.x * blockDim.x + threadIdx.x) >> 5;
    const int nwarps = (gridDim.x * blockDim.x) >> 5;

    for (int g = warpId; g < NG; g += nwarps) {
        float we = (lane < EPG) ? ew[g * EPG + lane] : 0.f;
        const float* xg = x + (size_t)g * (NPG * FD);
        #pragma unroll
        for (int r = 0; r < 3; r++) { int i = lane + r * 32; if (i < NPG * FD) sx[i] = xg[i]; }

        float dv[6]; dinv6(we, lane, dv);
        if (lane < EPG) {
            int s = lane / 5, j = lane - s * 5, t = j + (j >= s);
            sA[t * 6 + s] = dv[t] * we * dv[s];
        }
        if (lane < 6) sA[lane * 7] = dv[lane] * dv[lane];
        __syncwarp();

        // xa[t][c] = sum_s A[t][s] * x[s][c]
        #pragma unroll
        for (int r = 0; r < 3; r++) {
            int i = lane + r * 32;
            if (i < NPG * FD) {
                int t = i / FD, c = i - t * FD;
                float v = 0.f;
                #pragma unroll
                for (int s = 0; s < 6; s++) v = fmaf(sA[t * 6 + s], sx[s * FD + c], v);
                sxa[i] = v;
            }
        }
        __syncwarp();

        float* outp = g_h1 + (size_t)g * (NPG * HD) + lane;
        #pragma unroll
        for (int t = 0; t < NPG; t++) {
            float acc = b1l;
            #pragma unroll
            for (int c = 0; c < FD; c++) acc = fmaf(sxa[t * FD + c], w1c[c], acc);
            outp[t * HD] = acc;
            ssum += acc;
            ssq = fmaf(acc, acc, ssq);
        }
        __syncwarp();
    }

    sred[w][lane] = ssum; sred[w][32 + lane] = ssq;
    __syncthreads();
    if (threadIdx.x < 64) {
        float tot = 0.f;
        #pragma unroll
        for (int i = 0; i < 8; i++) tot += sred[i][threadIdx.x];
        if (threadIdx.x < 32) atomicAdd(&g_sum1[threadIdx.x], tot);
        else                  atomicAdd(&g_sq1[threadIdx.x - 32], tot);
    }
}

// ---------------- finalize BN params ----------------
__global__ void k_bn(const float* __restrict__ gam, const float* __restrict__ bet, int which) {
    int f = threadIdx.x;
    if (f < HD) {
        float n = (float)NN;
        float s  = which ? g_sum2[f] : g_sum1[f];
        float sq = which ? g_sq2[f]  : g_sq1[f];
        float mean = s / n;
        float var = sq / n - mean * mean;
        if (var < 0.f) var = 0.f;
        float sc = gam[f] * rsqrtf(var + BNEPS);
        float sh = bet[f] - mean * sc;
        if (which) { g_scale2[f] = sc; g_shift2[f] = sh; }
        else       { g_scale1[f] = sc; g_shift1[f] = sh; }
    }
}

// ---------------- K3: h1 = relu(bn1(h1_pre)); h2_pre = (A@h1)@W2 + b2 ; BN2 stats ----------------
__global__ void __launch_bounds__(256) k3(const float* __restrict__ ew,
                                          const float* __restrict__ W2,
                                          const float* __restrict__ b2) {
    __shared__ float sbuf[8][240];   // per warp: sA[0..35], sha[48..239]
    __shared__ float sred[8][64];
    const int lane = threadIdx.x & 31, w = threadIdx.x >> 5;
    float* sA  = sbuf[w];
    float* sha = sbuf[w] + 48;

    float w2c[HD];
    #pragma unroll
    for (int c = 0; c < HD; c++) w2c[c] = W2[c * HD + lane];
    const float b2l = b2[lane];
    const float s1 = g_scale1[lane], sh1 = g_shift1[lane];

    float ssum = 0.f, ssq = 0.f;
    const int warpId = (blockIdx.x * blockDim.x + threadIdx.x) >> 5;
    const int nwarps = (gridDim.x * blockDim.x) >> 5;

    for (int g = warpId; g < NG; g += nwarps) {
        float we = (lane < EPG) ? ew[g * EPG + lane] : 0.f;
        float dv[6]; dinv6(we, lane, dv);
        if (lane < EPG) {
            int s = lane / 5, j = lane - s * 5, t = j + (j >= s);
            sA[t * 6 + s] = dv[t] * we * dv[s];
        }
        if (lane < 6) sA[lane * 7] = dv[lane] * dv[lane];

        const float* hp = g_h1 + (size_t)g * (NPG * HD) + lane;
        float h[NPG];
        #pragma unroll
        for (int t = 0; t < NPG; t++) h[t] = fmaxf(0.f, fmaf(hp[t * HD], s1, sh1));
        __syncwarp();

        // ha[t] (this lane's feature) = sum_s A[t][s] * h[s]
        #pragma unroll
        for (int t = 0; t < NPG; t++) {
            float v = 0.f;
            #pragma unroll
            for (int s = 0; s < 6; s++) v = fmaf(sA[t * 6 + s], h[s], v);
            sha[t * HD + lane] = v;
        }
        __syncwarp();

        float* outp = g_h2 + (size_t)g * (NPG * HD) + lane;
        #pragma unroll
        for (int t = 0; t < NPG; t++) {
            float acc = b2l;
            #pragma unroll
            for (int c = 0; c < HD; c++) acc = fmaf(sha[t * HD + c], w2c[c], acc);
            outp[t * HD] = acc;
            ssum += acc;
            ssq = fmaf(acc, acc, ssq);
        }
        __syncwarp();
    }

    sred[w][lane] = ssum; sred[w][32 + lane] = ssq;
    __syncthreads();
    if (threadIdx.x < 64) {
        float tot = 0.f;
        #pragma unroll
        for (int i = 0; i < 8; i++) tot += sred[i][threadIdx.x];
        if (threadIdx.x < 32) atomicAdd(&g_sum2[threadIdx.x], tot);
        else                  atomicAdd(&g_sq2[threadIdx.x - 32], tot);
    }
}

// ---------------- K5: bn2+relu, mean-pool, readout, sigmoid ----------------
__global__ void __launch_bounds__(256) k5(const float* __restrict__ gf,
                                          const float* __restrict__ Wo,
                                          const float* __restrict__ bo,
                                          const float* __restrict__ Wb,
                                          const float* __restrict__ bb,
                                          float* __restrict__ out) {
    const int lane = threadIdx.x & 31;
    const int g = (blockIdx.x * blockDim.x + threadIdx.x) >> 5;
    if (g >= NG) return;

    const float s2 = g_scale2[lane], sh2 = g_shift2[lane];
    const float wol = Wo[lane], wbl = Wb[lane];
    const float wog = (lane < GD) ? Wo[HD + lane] : 0.f;
    const float wbg = (lane < GD) ? Wb[HD + lane] : 0.f;

    const float* hp = g_h2 + (size_t)g * (NPG * HD) + lane;
    float p = 0.f;
    #pragma unroll
    for (int t = 0; t < NPG; t++) p += fmaxf(0.f, fmaf(hp[t * HD], s2, sh2));
    p *= (1.0f / 6.0f);

    float gv = (lane < GD) ? gf[g * GD + lane] : 0.f;
    float zo = fmaf(p, wol, gv * wog);
    float zb = fmaf(p, wbl, gv * wbg);
    #pragma unroll
    for (int o = 16; o; o >>= 1) {
        zo += __shfl_xor_sync(0xffffffffu, zo, o);
        zb += __shfl_xor_sync(0xffffffffu, zb, o);
    }
    if (lane == 0) {
        out[g]      = 1.0f / (1.0f + __expf(-(zo + bo[0])));
        out[NG + g] = 1.0f / (1.0f + __expf(-(zb + bb[0])));
    }
}

// ---------------- launch ----------------
extern "C" void kernel_launch(void* const* d_in, const int* in_sizes, int n_in,
                              void* d_out, int out_size) {
    const float* x   = (const float*)d_in[0];
    // d_in[1] edge_index, d_in[3] batch: topology is fixed -> unused
    const float* ew  = (const float*)d_in[2];
    const float* gf  = (const float*)d_in[4];
    const float* W1  = (const float*)d_in[5];
    const float* b1  = (const float*)d_in[6];
    const float* g1  = (const float*)d_in[7];
    const float* be1 = (const float*)d_in[8];
    const float* W2  = (const float*)d_in[9];
    const float* b2  = (const float*)d_in[10];
    const float* g2  = (const float*)d_in[11];
    const float* be2 = (const float*)d_in[12];
    const float* Wo  = (const float*)d_in[13];
    const float* bo  = (const float*)d_in[14];
    const float* Wb  = (const float*)d_in[15];
    const float* bb  = (const float*)d_in[16];
    float* out = (float*)d_out;

    k_zero_stats<<<1, 64>>>();
    k1<<<2048, 256>>>(x, ew, W1, b1);
    k_bn<<<1, 32>>>(g1, be1, 0);
    k3<<<2048, 256>>>(ew, W2, b2);
    k_bn<<<1, 32>>>(g2, be2, 1);
    k5<<<NG / 8, 256>>>(gf, Wo, bo, Wb, bb, out);
}